// round 11
// baseline (speedup 1.0000x reference)
#include <cuda_runtime.h>
#include <cuda_bf16.h>
#include <cstdint>
#include <math.h>

#define EPS 1e-8f

// Scratch (device globals: no allocation allowed)
__device__ float g_att[2][16][128][128];       // attention matrices (fw/bw)
__device__ float g_rowsum_fw[16][128];         // sum_j att_fw[b,i,j]
__device__ float g_meanS[2][16][128][256];     // att @ q2 (unnormalized mean)
__device__ float g_maxat[2][16][128][256];     // max_j att[i,j]*q2[j,h]
__device__ __nv_bfloat16 g_q2h[16 * 128 * 512];  // q2 hi bf16
__device__ __nv_bfloat16 g_q2l[16 * 128 * 512];  // q2 lo bf16 (residual)

// ---------------------------------------------------------------------------
// mma.sync m16n8k16 bf16 (HMMA path — legal on plain sm_103 PTX target)
// ---------------------------------------------------------------------------
__device__ __forceinline__ void mma16816(float* d, const uint32_t* a, const uint32_t* b) {
    asm volatile(
        "mma.sync.aligned.m16n8k16.row.col.f32.bf16.bf16.f32 "
        "{%0,%1,%2,%3}, {%4,%5,%6,%7}, {%8,%9}, {%0,%1,%2,%3};"
        : "+f"(d[0]), "+f"(d[1]), "+f"(d[2]), "+f"(d[3])
        : "r"(a[0]), "r"(a[1]), "r"(a[2]), "r"(a[3]), "r"(b[0]), "r"(b[1]));
}

// ---------------------------------------------------------------------------
// Kernel 0: split q2 into hi/lo bf16 (p-independent, done once)
// ---------------------------------------------------------------------------
__global__ void k_split_q2(const float* __restrict__ q2) {
    int idx = blockIdx.x * 256 + threadIdx.x;    // 262144 float4 groups
    float4 v = *(const float4*)(q2 + (size_t)idx * 4);
    __nv_bfloat16 h0 = __float2bfloat16(v.x), h1 = __float2bfloat16(v.y);
    __nv_bfloat16 h2 = __float2bfloat16(v.z), h3 = __float2bfloat16(v.w);
    __nv_bfloat16 l0 = __float2bfloat16(v.x - __bfloat162float(h0));
    __nv_bfloat16 l1 = __float2bfloat16(v.y - __bfloat162float(h1));
    __nv_bfloat16 l2 = __float2bfloat16(v.z - __bfloat162float(h2));
    __nv_bfloat16 l3 = __float2bfloat16(v.w - __bfloat162float(h3));
    uint2 pk;
    pk.x = ((uint32_t)__bfloat16_as_ushort(h1) << 16) | __bfloat16_as_ushort(h0);
    pk.y = ((uint32_t)__bfloat16_as_ushort(h3) << 16) | __bfloat16_as_ushort(h2);
    ((uint2*)g_q2h)[idx] = pk;
    pk.x = ((uint32_t)__bfloat16_as_ushort(l1) << 16) | __bfloat16_as_ushort(l0);
    pk.y = ((uint32_t)__bfloat16_as_ushort(l3) << 16) | __bfloat16_as_ushort(l2);
    ((uint2*)g_q2l)[idx] = pk;
}

// ---------------------------------------------------------------------------
// Kernel 1: attention matrices
// ---------------------------------------------------------------------------
__global__ void k_attention(const float* __restrict__ q1, const float* __restrict__ q2) {
    int b = blockIdx.x, dir = blockIdx.y;
    int it = blockIdx.z >> 1, jt = blockIdx.z & 1;
    const float* A = q1 + ((size_t)b * 128 + it * 64) * 512 + dir * 256;
    const float* B = q2 + ((size_t)b * 128 + jt * 64) * 512 + dir * 256;

    __shared__ float n1s[64], n2s[64];
    __shared__ float As[16][64], Bs[16][64];

    int t = threadIdx.x;
    if (t < 128) {
        int r = t & 63;
        const float* src = (t < 64) ? A : B;
        float s = 0.f;
        for (int h = 0; h < 256; h += 4) {
            float4 v = *(const float4*)(src + (size_t)r * 512 + h);
            s += v.x * v.x + v.y * v.y + v.z * v.z + v.w * v.w;
        }
        if (t < 64) n1s[r] = sqrtf(s); else n2s[r] = sqrtf(s);
    }

    int tx = t & 15, ty = t >> 4;
    float acc[4][4] = {};
    int iL = t >> 2, c4 = (t & 3) * 4;

    for (int k0 = 0; k0 < 256; k0 += 16) {
        float4 a  = *(const float4*)(A + (size_t)iL * 512 + k0 + c4);
        float4 bb = *(const float4*)(B + (size_t)iL * 512 + k0 + c4);
        As[c4 + 0][iL] = a.x;  As[c4 + 1][iL] = a.y;
        As[c4 + 2][iL] = a.z;  As[c4 + 3][iL] = a.w;
        Bs[c4 + 0][iL] = bb.x; Bs[c4 + 1][iL] = bb.y;
        Bs[c4 + 2][iL] = bb.z; Bs[c4 + 3][iL] = bb.w;
        __syncthreads();
#pragma unroll
        for (int kk = 0; kk < 16; kk++) {
            float4 ar = *(const float4*)&As[kk][ty * 4];
            float4 br = *(const float4*)&Bs[kk][tx * 4];
            float arr[4] = {ar.x, ar.y, ar.z, ar.w};
            float brr[4] = {br.x, br.y, br.z, br.w};
#pragma unroll
            for (int ii = 0; ii < 4; ii++)
#pragma unroll
                for (int jj = 0; jj < 4; jj++)
                    acc[ii][jj] += arr[ii] * brr[jj];
        }
        __syncthreads();
    }

#pragma unroll
    for (int ii = 0; ii < 4; ii++)
#pragma unroll
        for (int jj = 0; jj < 4; jj++) {
            int i = ty * 4 + ii, j = tx * 4 + jj;
            float den = n1s[i] * n2s[j];
            den = (den > EPS) ? den : EPS;
            g_att[dir][b][it * 64 + i][jt * 64 + j] = acc[ii][jj] / den;
        }
}

// ---------------------------------------------------------------------------
// Kernel 1.5: rowsums of att_fw
// ---------------------------------------------------------------------------
__global__ void k_rowsum() {
    int b = blockIdx.x, i = threadIdx.x;
    float s = 0.f;
    const float* row = &g_att[0][b][i][0];
    for (int j = 0; j < 128; j++) s += row[j];
    g_rowsum_fw[b][i] = s;
}

// ---------------------------------------------------------------------------
// Kernel 2: meanS / maxat — j-outer, register accumulators.
// grid (16 b, 2 dir, 16 iq) = 512 CTAs; 8 i-rows per CTA; thread = h.
// Per j: 1 LDG (q2[j,h], coalesced) + 8 FMA + 8 FMAX + 4 LDS.64 (broadcast).
// ---------------------------------------------------------------------------
__global__ void __launch_bounds__(256)
k_meanmax(const float* __restrict__ q2) {
    int b = blockIdx.x, dir = blockIdx.y, iq = blockIdx.z;
    int i0 = iq * 8;
    __shared__ float2 att_s[8][64];     // att rows as float2 pairs (j/2)

    // load 8 att rows (8*128 floats = 512 float2)
    const float* src = &g_att[dir][b][i0][0];
    {
        int c = threadIdx.x;            // 256 threads, 2 rounds of float4
        float4 v0 = *(const float4*)(src + c * 4);
        ((float4*)att_s)[c] = v0;
    }
    __syncthreads();

    int h = threadIdx.x;
    const float* B = q2 + (size_t)b * 65536 + dir * 256 + h;

    float acc[8] = {};
    float mx[8] = {-INFINITY, -INFINITY, -INFINITY, -INFINITY,
                   -INFINITY, -INFINITY, -INFINITY, -INFINITY};

#pragma unroll 4
    for (int j2 = 0; j2 < 64; j2++) {
        float q0 = __ldg(B + (size_t)(2 * j2) * 512);
        float q1 = __ldg(B + (size_t)(2 * j2 + 1) * 512);
#pragma unroll
        for (int i = 0; i < 8; i++) {
            float2 a = att_s[i][j2];
            float v0 = a.x * q0;
            float v1 = a.y * q1;
            acc[i] += v0 + v1;
            mx[i] = fmaxf(mx[i], fmaxf(v0, v1));
        }
    }

#pragma unroll
    for (int i = 0; i < 8; i++) {
        g_meanS[dir][b][i0 + i][h] = acc[i];
        g_maxat[dir][b][i0 + i][h] = mx[i];
    }
}

// ---------------------------------------------------------------------------
// Kernel 3 (HMMA): cos_maxpool. One CTA per (b,p,dir).
// S = (q1 .* w2_p) q2^T via bf16 3-term split: Ah*Bh + Ah*Bl + Al*Bh.
// K=256 in 4 chunks of 64. SMEM tiles [128][72] bf16 (stride 36 words).
// ---------------------------------------------------------------------------
#define TS_W    36                       // padded tile stride in 32-bit words
#define TILE_B  (128 * TS_W * 4)         // 18432 bytes

#define OFF_W2   0
#define OFF_NA   1024
#define OFF_NC   1536
#define OFF_RED  2048
#define OFF_AH   4096
#define OFF_AL   (OFF_AH + TILE_B)
#define OFF_BH   (OFF_AH + 2 * TILE_B)
#define OFF_BL   (OFF_AH + 3 * TILE_B)
#define SMEM_MMA_TOTAL (OFF_AH + 4 * TILE_B)   // 77824

__global__ void __launch_bounds__(256)
k_maxpool_mma(const float* __restrict__ q1, const float* __restrict__ q2,
              const float* __restrict__ W, float* __restrict__ out) {
    extern __shared__ char smem[];
    int b = blockIdx.x, p = blockIdx.y, dir = blockIdx.z;
    int t = threadIdx.x;
    int wid = t >> 5, lane = t & 31;
    int gid = lane >> 2, tig = lane & 3;
    int wr = wid >> 2, wc = wid & 3;       // warp grid 2x4
    int mb = wr * 64, nb = wc * 32;        // warp tile bases

    const float* Ag = q1 + (size_t)b * 65536 + dir * 256;   // row stride 512
    const float* Bg = q2 + (size_t)b * 65536 + dir * 256;
    const float* Wp = W + (size_t)((2 + dir) * 16 + p) * 256;

    float* w2s  = (float*)(smem + OFF_W2);
    float* na_s = (float*)(smem + OFF_NA);
    float* nc_s = (float*)(smem + OFF_NC);
    float* red  = (float*)(smem + OFF_RED);          // [128][4]
    uint32_t* Ah_w = (uint32_t*)(smem + OFF_AH);
    uint32_t* Al_w = (uint32_t*)(smem + OFF_AL);
    uint32_t* Bh_w = (uint32_t*)(smem + OFF_BH);
    uint32_t* Bl_w = (uint32_t*)(smem + OFF_BL);

    { float w = Wp[t]; w2s[t] = w * w; }
    __syncthreads();

    // exact fp32 weighted norms
    {
        int r = t & 127;
        const float* src = (t < 128) ? Ag : Bg;
        float s = 0.f;
        for (int h = 0; h < 256; h += 4) {
            float4 v = *(const float4*)(src + (size_t)r * 512 + h);
            s += v.x * v.x * w2s[h] + v.y * v.y * w2s[h + 1]
               + v.z * v.z * w2s[h + 2] + v.w * v.w * w2s[h + 3];
        }
        if (t < 128) na_s[r] = sqrtf(s); else nc_s[r] = sqrtf(s);
    }

    float acc[4][4][4];
#pragma unroll
    for (int mi = 0; mi < 4; mi++)
#pragma unroll
        for (int ni = 0; ni < 4; ni++)
#pragma unroll
            for (int c = 0; c < 4; c++) acc[mi][ni][c] = 0.f;

    const __nv_bfloat16* q2h_base = g_q2h + ((size_t)b * 128) * 512 + dir * 256;
    const __nv_bfloat16* q2l_base = g_q2l + ((size_t)b * 128) * 512 + dir * 256;

    for (int c = 0; c < 4; c++) {
        int kb = c * 64;
        // ---- convert A chunk (q1 .* w2), split hi/lo ----
#pragma unroll
        for (int r = 0; r < 8; r++) {
            int v = r * 256 + t;             // 0..2047
            int i = v >> 4;                  // row 0..127
            int h4 = (v & 15) * 4;           // 0..60
            float4 qa = *(const float4*)(Ag + (size_t)i * 512 + kb + h4);
            float a0 = qa.x * w2s[kb + h4 + 0];
            float a1 = qa.y * w2s[kb + h4 + 1];
            float a2 = qa.z * w2s[kb + h4 + 2];
            float a3 = qa.w * w2s[kb + h4 + 3];
            __nv_bfloat16 h0 = __float2bfloat16(a0), h1 = __float2bfloat16(a1);
            __nv_bfloat16 h2 = __float2bfloat16(a2), h3 = __float2bfloat16(a3);
            __nv_bfloat16 l0 = __float2bfloat16(a0 - __bfloat162float(h0));
            __nv_bfloat16 l1 = __float2bfloat16(a1 - __bfloat162float(h1));
            __nv_bfloat16 l2 = __float2bfloat16(a2 - __bfloat162float(h2));
            __nv_bfloat16 l3 = __float2bfloat16(a3 - __bfloat162float(h3));
            uint32_t woff = (uint32_t)i * TS_W + (uint32_t)(h4 >> 1);
            uint2 pk;
            pk.x = ((uint32_t)__bfloat16_as_ushort(h1) << 16) | __bfloat16_as_ushort(h0);
            pk.y = ((uint32_t)__bfloat16_as_ushort(h3) << 16) | __bfloat16_as_ushort(h2);
            *(uint2*)(Ah_w + woff) = pk;
            pk.x = ((uint32_t)__bfloat16_as_ushort(l1) << 16) | __bfloat16_as_ushort(l0);
            pk.y = ((uint32_t)__bfloat16_as_ushort(l3) << 16) | __bfloat16_as_ushort(l2);
            *(uint2*)(Al_w + woff) = pk;
        }
        // ---- copy precomputed B chunk (hi/lo bf16) ----
#pragma unroll
        for (int r = 0; r < 8; r++) {
            int v = r * 256 + t;
            int n = v >> 4;
            int kk = (v & 15) * 4;
            uint32_t woff = (uint32_t)n * TS_W + (uint32_t)(kk >> 1);
            *(uint2*)(Bh_w + woff) = *(const uint2*)(q2h_base + (size_t)n * 512 + kb + kk);
            *(uint2*)(Bl_w + woff) = *(const uint2*)(q2l_base + (size_t)n * 512 + kb + kk);
        }
        __syncthreads();

        // ---- MMA over this chunk: 4 k-steps of 16 ----
#pragma unroll
        for (int ks = 0; ks < 4; ks++) {
            int kw = ks * 8;     // k offset in words
            uint32_t bhf[4][2], blf[4][2];
#pragma unroll
            for (int ni = 0; ni < 4; ni++) {
                const uint32_t* ph = Bh_w + (uint32_t)(nb + ni * 8 + gid) * TS_W + kw + tig;
                bhf[ni][0] = ph[0]; bhf[ni][1] = ph[4];
                const uint32_t* pl = Bl_w + (uint32_t)(nb + ni * 8 + gid) * TS_W + kw + tig;
                blf[ni][0] = pl[0]; blf[ni][1] = pl[4];
            }
#pragma unroll
            for (int mi = 0; mi < 4; mi++) {
                const uint32_t* pa = Ah_w + (uint32_t)(mb + mi * 16 + gid) * TS_W + kw + tig;
                uint32_t ah[4];
                ah[0] = pa[0]; ah[1] = pa[8 * TS_W];
                ah[2] = pa[4]; ah[3] = pa[8 * TS_W + 4];
                const uint32_t* pl = Al_w + (uint32_t)(mb + mi * 16 + gid) * TS_W + kw + tig;
                uint32_t al[4];
                al[0] = pl[0]; al[1] = pl[8 * TS_W];
                al[2] = pl[4]; al[3] = pl[8 * TS_W + 4];
#pragma unroll
                for (int ni = 0; ni < 4; ni++) {
                    mma16816(acc[mi][ni], ah, bhf[ni]);
                    mma16816(acc[mi][ni], ah, blf[ni]);
                    mma16816(acc[mi][ni], al, bhf[ni]);
                }
            }
        }
        __syncthreads();
    }

    // ---- epilogue: cos divide + row max ----
    float nc_v[4][2];
#pragma unroll
    for (int ni = 0; ni < 4; ni++) {
        int cb = nb + ni * 8 + 2 * tig;
        nc_v[ni][0] = nc_s[cb];
        nc_v[ni][1] = nc_s[cb + 1];
    }
#pragma unroll
    for (int mi = 0; mi < 4; mi++) {
        int r0 = mb + mi * 16 + gid;
        float na0 = na_s[r0], na1 = na_s[r0 + 8];
        float m0 = -INFINITY, m1 = -INFINITY;
#pragma unroll
        for (int ni = 0; ni < 4; ni++) {
            m0 = fmaxf(m0, acc[mi][ni][0] / fmaxf(na0 * nc_v[ni][0], EPS));
            m0 = fmaxf(m0, acc[mi][ni][1] / fmaxf(na0 * nc_v[ni][1], EPS));
            m1 = fmaxf(m1, acc[mi][ni][2] / fmaxf(na1 * nc_v[ni][0], EPS));
            m1 = fmaxf(m1, acc[mi][ni][3] / fmaxf(na1 * nc_v[ni][1], EPS));
        }
        m0 = fmaxf(m0, __shfl_xor_sync(0xffffffffu, m0, 1));
        m0 = fmaxf(m0, __shfl_xor_sync(0xffffffffu, m0, 2));
        m1 = fmaxf(m1, __shfl_xor_sync(0xffffffffu, m1, 1));
        m1 = fmaxf(m1, __shfl_xor_sync(0xffffffffu, m1, 2));
        if (tig == 0) {
            red[r0 * 4 + wc] = m0;
            red[(r0 + 8) * 4 + wc] = m1;
        }
    }
    __syncthreads();
    if (t < 128) {
        float m = red[t * 4 + 0];
        m = fmaxf(m, red[t * 4 + 1]);
        m = fmaxf(m, red[t * 4 + 2]);
        m = fmaxf(m, red[t * 4 + 3]);
        out[((size_t)b * 128 + t) * 128 + 32 + dir * 16 + p] = m;
    }
}

// ---------------------------------------------------------------------------
// Kernel 4: the six cos_full outputs
// ---------------------------------------------------------------------------
__global__ void k_cosfull(const float* __restrict__ q1, const float* __restrict__ q2,
                          const float* __restrict__ W, float* __restrict__ out) {
    int i = blockIdx.x, b = blockIdx.y;
    int lane = threadIdx.x & 31, warp = threadIdx.x >> 5;

    for (int s = 0; s < 12; s++) {
        int tk = warp + 8 * s;
        int p = tk & 15;
        int rest = tk >> 4;
        int dir = rest & 1, which = rest >> 1;
        int widx = (which == 0) ? dir : ((which == 1) ? 4 + dir : 6 + dir);
        const float* wv = W + (size_t)(widx * 16 + p) * 256;
        const float* x  = q1 + (size_t)b * 65536 + (size_t)i * 512 + dir * 256;
        const float* y;
        float sy = 1.f;
        if (which == 0) {
            int j = (dir == 0) ? 127 : 0;
            y = q2 + (size_t)b * 65536 + (size_t)j * 512 + dir * 256;
        } else if (which == 1) {
            y = &g_meanS[dir][b][i][0];
            float rs = g_rowsum_fw[b][i];
            float bsafe = (rs > EPS) ? rs : EPS;
            sy = 1.f / bsafe;
        } else {
            y = &g_maxat[dir][b][i][0];
        }

        float sxy = 0.f, sxx = 0.f, syy = 0.f;
        for (int h = lane; h < 256; h += 32) {
            float w = wv[h]; float ww = w * w;
            float xv = x[h];
            float yv = y[h] * sy;
            sxy += xv * yv * ww;
            sxx += xv * xv * ww;
            syy += yv * yv * ww;
        }
#pragma unroll
        for (int off = 16; off > 0; off >>= 1) {
            sxy += __shfl_xor_sync(0xffffffffu, sxy, off);
            sxx += __shfl_xor_sync(0xffffffffu, sxx, off);
            syy += __shfl_xor_sync(0xffffffffu, syy, off);
        }
        if (lane == 0) {
            float den = fmaxf(sqrtf(sxx) * sqrtf(syy), EPS);
            int col = ((which == 0) ? 0 : (which == 1) ? 64 : 96) + dir * 16 + p;
            out[((size_t)b * 128 + i) * 128 + col] = sxy / den;
        }
    }
}

// ---------------------------------------------------------------------------
extern "C" void kernel_launch(void* const* d_in, const int* in_sizes, int n_in,
                              void* d_out, int out_size) {
    const float* q1 = (const float*)d_in[0];
    const float* q2 = (const float*)d_in[1];
    const float* W  = (const float*)d_in[2];
    float* out = (float*)d_out;

    cudaFuncSetAttribute(k_maxpool_mma, cudaFuncAttributeMaxDynamicSharedMemorySize,
                         SMEM_MMA_TOTAL);

    k_split_q2<<<1024, 256>>>(q2);
    k_attention<<<dim3(16, 2, 4), 256>>>(q1, q2);
    k_rowsum<<<16, 128>>>();
    k_meanmax<<<dim3(16, 2, 16), 256>>>(q2);
    k_maxpool_mma<<<dim3(16, 16, 2), 256, SMEM_MMA_TOTAL>>>(q1, q2, W, out);
    k_cosfull<<<dim3(128, 16), 256>>>(q1, q2, W, out);
}

// round 12
// speedup vs baseline: 1.0208x; 1.0208x over previous
#include <cuda_runtime.h>
#include <cuda_bf16.h>
#include <cstdint>
#include <math.h>

#define EPS 1e-8f

// Scratch (device globals: no allocation allowed)
__device__ float g_att[2][16][128][128];       // attention matrices (fw/bw)
__device__ float g_rowsum_fw[16][128];         // sum_j att_fw[b,i,j]
__device__ float g_meanS[2][16][128][256];     // att @ q2 (unnormalized mean)
__device__ float g_maxat[2][16][128][256];     // max_j att[i,j]*q2[j,h]
__device__ __nv_bfloat16 g_q1h[16 * 128 * 512];  // q1 hi bf16
__device__ __nv_bfloat16 g_q1l[16 * 128 * 512];  // q1 lo bf16
__device__ __nv_bfloat16 g_q2h[16 * 128 * 512];  // q2 hi bf16
__device__ __nv_bfloat16 g_q2l[16 * 128 * 512];  // q2 lo bf16

// ---------------------------------------------------------------------------
// mma.sync m16n8k16 bf16 (HMMA path — legal on plain sm_103 PTX target)
// ---------------------------------------------------------------------------
__device__ __forceinline__ void mma16816(float* d, const uint32_t* a, const uint32_t* b) {
    asm volatile(
        "mma.sync.aligned.m16n8k16.row.col.f32.bf16.bf16.f32 "
        "{%0,%1,%2,%3}, {%4,%5,%6,%7}, {%8,%9}, {%0,%1,%2,%3};"
        : "+f"(d[0]), "+f"(d[1]), "+f"(d[2]), "+f"(d[3])
        : "r"(a[0]), "r"(a[1]), "r"(a[2]), "r"(a[3]), "r"(b[0]), "r"(b[1]));
}

// ---------------------------------------------------------------------------
// Kernel 0: split q1 AND q2 into hi/lo bf16 (done once)
// grid 2048 x 256; first half handles q1, second half q2
// ---------------------------------------------------------------------------
__global__ void k_split(const float* __restrict__ q1, const float* __restrict__ q2) {
    int gidx = blockIdx.x * 256 + threadIdx.x;   // 0 .. 524287
    int which = gidx >> 18;                      // 0 = q1, 1 = q2
    int idx = gidx & 0x3FFFF;                    // 0 .. 262143 float4 groups
    const float* src = which ? q2 : q1;
    float4 v = *(const float4*)(src + (size_t)idx * 4);
    __nv_bfloat16 h0 = __float2bfloat16(v.x), h1 = __float2bfloat16(v.y);
    __nv_bfloat16 h2 = __float2bfloat16(v.z), h3 = __float2bfloat16(v.w);
    __nv_bfloat16 l0 = __float2bfloat16(v.x - __bfloat162float(h0));
    __nv_bfloat16 l1 = __float2bfloat16(v.y - __bfloat162float(h1));
    __nv_bfloat16 l2 = __float2bfloat16(v.z - __bfloat162float(h2));
    __nv_bfloat16 l3 = __float2bfloat16(v.w - __bfloat162float(h3));
    uint2 pk;
    pk.x = ((uint32_t)__bfloat16_as_ushort(h1) << 16) | __bfloat16_as_ushort(h0);
    pk.y = ((uint32_t)__bfloat16_as_ushort(h3) << 16) | __bfloat16_as_ushort(h2);
    ((uint2*)(which ? g_q2h : g_q1h))[idx] = pk;
    pk.x = ((uint32_t)__bfloat16_as_ushort(l1) << 16) | __bfloat16_as_ushort(l0);
    pk.y = ((uint32_t)__bfloat16_as_ushort(l3) << 16) | __bfloat16_as_ushort(l2);
    ((uint2*)(which ? g_q2l : g_q1l))[idx] = pk;
}

// ---------------------------------------------------------------------------
// Shared tile geometry for the two HMMA kernels
// ---------------------------------------------------------------------------
#define TS_W    36                       // padded tile stride in 32-bit words
#define TILE_B  (128 * TS_W * 4)         // 18432 bytes

// ---------------------------------------------------------------------------
// Kernel 1 (HMMA): attention + fused rowsum.
// One CTA per (b, dir). att = q1 q2^T / clamp(n1 n2). 3-term bf16 split.
// ---------------------------------------------------------------------------
#define AOFF_NA   0
#define AOFF_NC   512
#define AOFF_RED  1024
#define AOFF_AH   4096
#define AOFF_AL   (AOFF_AH + TILE_B)
#define AOFF_BH   (AOFF_AH + 2 * TILE_B)
#define AOFF_BL   (AOFF_AH + 3 * TILE_B)
#define SMEM_ATT_TOTAL (AOFF_AH + 4 * TILE_B)   // 77824

__global__ void __launch_bounds__(256)
k_attention_mma(const float* __restrict__ q1, const float* __restrict__ q2) {
    extern __shared__ char smem[];
    int b = blockIdx.x, dir = blockIdx.y;
    int t = threadIdx.x;
    int wid = t >> 5, lane = t & 31;
    int gid = lane >> 2, tig = lane & 3;
    int wr = wid >> 2, wc = wid & 3;       // warp grid 2x4
    int mb = wr * 64, nb = wc * 32;

    const float* Ag = q1 + (size_t)b * 65536 + dir * 256;
    const float* Bg = q2 + (size_t)b * 65536 + dir * 256;

    float* n1_s = (float*)(smem + AOFF_NA);
    float* n2_s = (float*)(smem + AOFF_NC);
    float* red  = (float*)(smem + AOFF_RED);          // [128][4]
    uint32_t* Ah_w = (uint32_t*)(smem + AOFF_AH);
    uint32_t* Al_w = (uint32_t*)(smem + AOFF_AL);
    uint32_t* Bh_w = (uint32_t*)(smem + AOFF_BH);
    uint32_t* Bl_w = (uint32_t*)(smem + AOFF_BL);

    // exact fp32 norms
    {
        int r = t & 127;
        const float* src = (t < 128) ? Ag : Bg;
        float s = 0.f;
        for (int h = 0; h < 256; h += 4) {
            float4 v = *(const float4*)(src + (size_t)r * 512 + h);
            s += v.x * v.x + v.y * v.y + v.z * v.z + v.w * v.w;
        }
        if (t < 128) n1_s[r] = sqrtf(s); else n2_s[r] = sqrtf(s);
    }

    float acc[4][4][4];
#pragma unroll
    for (int mi = 0; mi < 4; mi++)
#pragma unroll
        for (int ni = 0; ni < 4; ni++)
#pragma unroll
            for (int c = 0; c < 4; c++) acc[mi][ni][c] = 0.f;

    const __nv_bfloat16* q1h_base = g_q1h + ((size_t)b * 128) * 512 + dir * 256;
    const __nv_bfloat16* q1l_base = g_q1l + ((size_t)b * 128) * 512 + dir * 256;
    const __nv_bfloat16* q2h_base = g_q2h + ((size_t)b * 128) * 512 + dir * 256;
    const __nv_bfloat16* q2l_base = g_q2l + ((size_t)b * 128) * 512 + dir * 256;

    for (int c = 0; c < 4; c++) {
        int kb = c * 64;
        // ---- copy precomputed A and B chunks (hi/lo bf16) ----
#pragma unroll
        for (int r = 0; r < 8; r++) {
            int v = r * 256 + t;
            int n = v >> 4;
            int kk = (v & 15) * 4;
            uint32_t woff = (uint32_t)n * TS_W + (uint32_t)(kk >> 1);
            *(uint2*)(Ah_w + woff) = *(const uint2*)(q1h_base + (size_t)n * 512 + kb + kk);
            *(uint2*)(Al_w + woff) = *(const uint2*)(q1l_base + (size_t)n * 512 + kb + kk);
            *(uint2*)(Bh_w + woff) = *(const uint2*)(q2h_base + (size_t)n * 512 + kb + kk);
            *(uint2*)(Bl_w + woff) = *(const uint2*)(q2l_base + (size_t)n * 512 + kb + kk);
        }
        __syncthreads();

#pragma unroll
        for (int ks = 0; ks < 4; ks++) {
            int kw = ks * 8;
            uint32_t bhf[4][2], blf[4][2];
#pragma unroll
            for (int ni = 0; ni < 4; ni++) {
                const uint32_t* ph = Bh_w + (uint32_t)(nb + ni * 8 + gid) * TS_W + kw + tig;
                bhf[ni][0] = ph[0]; bhf[ni][1] = ph[4];
                const uint32_t* pl = Bl_w + (uint32_t)(nb + ni * 8 + gid) * TS_W + kw + tig;
                blf[ni][0] = pl[0]; blf[ni][1] = pl[4];
            }
#pragma unroll
            for (int mi = 0; mi < 4; mi++) {
                const uint32_t* pa = Ah_w + (uint32_t)(mb + mi * 16 + gid) * TS_W + kw + tig;
                uint32_t ah[4];
                ah[0] = pa[0]; ah[1] = pa[8 * TS_W];
                ah[2] = pa[4]; ah[3] = pa[8 * TS_W + 4];
                const uint32_t* pl = Al_w + (uint32_t)(mb + mi * 16 + gid) * TS_W + kw + tig;
                uint32_t al[4];
                al[0] = pl[0]; al[1] = pl[8 * TS_W];
                al[2] = pl[4]; al[3] = pl[8 * TS_W + 4];
#pragma unroll
                for (int ni = 0; ni < 4; ni++) {
                    mma16816(acc[mi][ni], ah, bhf[ni]);
                    mma16816(acc[mi][ni], ah, blf[ni]);
                    mma16816(acc[mi][ni], al, bhf[ni]);
                }
            }
        }
        __syncthreads();
    }

    // ---- epilogue: normalize, store att, fused rowsum ----
    float n2v[4][2];
#pragma unroll
    for (int ni = 0; ni < 4; ni++) {
        int cb = nb + ni * 8 + 2 * tig;
        n2v[ni][0] = n2_s[cb];
        n2v[ni][1] = n2_s[cb + 1];
    }
#pragma unroll
    for (int mi = 0; mi < 4; mi++) {
        int r0 = mb + mi * 16 + gid;
        float na0 = n1_s[r0], na1 = n1_s[r0 + 8];
        float s0 = 0.f, s1 = 0.f;
#pragma unroll
        for (int ni = 0; ni < 4; ni++) {
            int cb = nb + ni * 8 + 2 * tig;
            float d00 = na0 * n2v[ni][0]; d00 = (d00 > EPS) ? d00 : EPS;
            float d01 = na0 * n2v[ni][1]; d01 = (d01 > EPS) ? d01 : EPS;
            float d10 = na1 * n2v[ni][0]; d10 = (d10 > EPS) ? d10 : EPS;
            float d11 = na1 * n2v[ni][1]; d11 = (d11 > EPS) ? d11 : EPS;
            float a00 = acc[mi][ni][0] / d00;
            float a01 = acc[mi][ni][1] / d01;
            float a10 = acc[mi][ni][2] / d10;
            float a11 = acc[mi][ni][3] / d11;
            *(float2*)&g_att[dir][b][r0][cb]     = make_float2(a00, a01);
            *(float2*)&g_att[dir][b][r0 + 8][cb] = make_float2(a10, a11);
            s0 += a00 + a01;
            s1 += a10 + a11;
        }
        s0 += __shfl_xor_sync(0xffffffffu, s0, 1);
        s0 += __shfl_xor_sync(0xffffffffu, s0, 2);
        s1 += __shfl_xor_sync(0xffffffffu, s1, 1);
        s1 += __shfl_xor_sync(0xffffffffu, s1, 2);
        if (tig == 0) {
            red[r0 * 4 + wc] = s0;
            red[(r0 + 8) * 4 + wc] = s1;
        }
    }
    __syncthreads();
    if (dir == 0 && t < 128) {
        g_rowsum_fw[b][t] = red[t * 4 + 0] + red[t * 4 + 1]
                          + red[t * 4 + 2] + red[t * 4 + 3];
    }
}

// ---------------------------------------------------------------------------
// Kernel 2: meanS / maxat — j-outer, register accumulators.
// ---------------------------------------------------------------------------
__global__ void __launch_bounds__(256)
k_meanmax(const float* __restrict__ q2) {
    int b = blockIdx.x, dir = blockIdx.y, iq = blockIdx.z;
    int i0 = iq * 8;
    __shared__ float2 att_s[8][64];

    const float* src = &g_att[dir][b][i0][0];
    {
        int c = threadIdx.x;
        float4 v0 = *(const float4*)(src + c * 4);
        ((float4*)att_s)[c] = v0;
    }
    __syncthreads();

    int h = threadIdx.x;
    const float* B = q2 + (size_t)b * 65536 + dir * 256 + h;

    float acc[8] = {};
    float mx[8] = {-INFINITY, -INFINITY, -INFINITY, -INFINITY,
                   -INFINITY, -INFINITY, -INFINITY, -INFINITY};

#pragma unroll 4
    for (int j2 = 0; j2 < 64; j2++) {
        float q0 = __ldg(B + (size_t)(2 * j2) * 512);
        float q1 = __ldg(B + (size_t)(2 * j2 + 1) * 512);
#pragma unroll
        for (int i = 0; i < 8; i++) {
            float2 a = att_s[i][j2];
            float v0 = a.x * q0;
            float v1 = a.y * q1;
            acc[i] += v0 + v1;
            mx[i] = fmaxf(mx[i], fmaxf(v0, v1));
        }
    }

#pragma unroll
    for (int i = 0; i < 8; i++) {
        g_meanS[dir][b][i0 + i][h] = acc[i];
        g_maxat[dir][b][i0 + i][h] = mx[i];
    }
}

// ---------------------------------------------------------------------------
// Kernel 3 (HMMA): cos_maxpool. One CTA per (b,p,dir).
// ---------------------------------------------------------------------------
#define OFF_W2   0
#define OFF_NA   1024
#define OFF_NC   1536
#define OFF_RED  2048
#define OFF_AH   4096
#define OFF_AL   (OFF_AH + TILE_B)
#define OFF_BH   (OFF_AH + 2 * TILE_B)
#define OFF_BL   (OFF_AH + 3 * TILE_B)
#define SMEM_MMA_TOTAL (OFF_AH + 4 * TILE_B)   // 77824

__global__ void __launch_bounds__(256)
k_maxpool_mma(const float* __restrict__ q1, const float* __restrict__ q2,
              const float* __restrict__ W, float* __restrict__ out) {
    extern __shared__ char smem[];
    int b = blockIdx.x, p = blockIdx.y, dir = blockIdx.z;
    int t = threadIdx.x;
    int wid = t >> 5, lane = t & 31;
    int gid = lane >> 2, tig = lane & 3;
    int wr = wid >> 2, wc = wid & 3;
    int mb = wr * 64, nb = wc * 32;

    const float* Ag = q1 + (size_t)b * 65536 + dir * 256;
    const float* Bg = q2 + (size_t)b * 65536 + dir * 256;
    const float* Wp = W + (size_t)((2 + dir) * 16 + p) * 256;

    float* w2s  = (float*)(smem + OFF_W2);
    float* na_s = (float*)(smem + OFF_NA);
    float* nc_s = (float*)(smem + OFF_NC);
    float* red  = (float*)(smem + OFF_RED);
    uint32_t* Ah_w = (uint32_t*)(smem + OFF_AH);
    uint32_t* Al_w = (uint32_t*)(smem + OFF_AL);
    uint32_t* Bh_w = (uint32_t*)(smem + OFF_BH);
    uint32_t* Bl_w = (uint32_t*)(smem + OFF_BL);

    { float w = Wp[t]; w2s[t] = w * w; }
    __syncthreads();

    {
        int r = t & 127;
        const float* src = (t < 128) ? Ag : Bg;
        float s = 0.f;
        for (int h = 0; h < 256; h += 4) {
            float4 v = *(const float4*)(src + (size_t)r * 512 + h);
            s += v.x * v.x * w2s[h] + v.y * v.y * w2s[h + 1]
               + v.z * v.z * w2s[h + 2] + v.w * v.w * w2s[h + 3];
        }
        if (t < 128) na_s[r] = sqrtf(s); else nc_s[r] = sqrtf(s);
    }

    float acc[4][4][4];
#pragma unroll
    for (int mi = 0; mi < 4; mi++)
#pragma unroll
        for (int ni = 0; ni < 4; ni++)
#pragma unroll
            for (int c = 0; c < 4; c++) acc[mi][ni][c] = 0.f;

    const __nv_bfloat16* q2h_base = g_q2h + ((size_t)b * 128) * 512 + dir * 256;
    const __nv_bfloat16* q2l_base = g_q2l + ((size_t)b * 128) * 512 + dir * 256;

    for (int c = 0; c < 4; c++) {
        int kb = c * 64;
        // ---- convert A chunk (q1 .* w2), split hi/lo ----
#pragma unroll
        for (int r = 0; r < 8; r++) {
            int v = r * 256 + t;
            int i = v >> 4;
            int h4 = (v & 15) * 4;
            float4 qa = *(const float4*)(Ag + (size_t)i * 512 + kb + h4);
            float a0 = qa.x * w2s[kb + h4 + 0];
            float a1 = qa.y * w2s[kb + h4 + 1];
            float a2 = qa.z * w2s[kb + h4 + 2];
            float a3 = qa.w * w2s[kb + h4 + 3];
            __nv_bfloat16 h0 = __float2bfloat16(a0), h1 = __float2bfloat16(a1);
            __nv_bfloat16 h2 = __float2bfloat16(a2), h3 = __float2bfloat16(a3);
            __nv_bfloat16 l0 = __float2bfloat16(a0 - __bfloat162float(h0));
            __nv_bfloat16 l1 = __float2bfloat16(a1 - __bfloat162float(h1));
            __nv_bfloat16 l2 = __float2bfloat16(a2 - __bfloat162float(h2));
            __nv_bfloat16 l3 = __float2bfloat16(a3 - __bfloat162float(h3));
            uint32_t woff = (uint32_t)i * TS_W + (uint32_t)(h4 >> 1);
            uint2 pk;
            pk.x = ((uint32_t)__bfloat16_as_ushort(h1) << 16) | __bfloat16_as_ushort(h0);
            pk.y = ((uint32_t)__bfloat16_as_ushort(h3) << 16) | __bfloat16_as_ushort(h2);
            *(uint2*)(Ah_w + woff) = pk;
            pk.x = ((uint32_t)__bfloat16_as_ushort(l1) << 16) | __bfloat16_as_ushort(l0);
            pk.y = ((uint32_t)__bfloat16_as_ushort(l3) << 16) | __bfloat16_as_ushort(l2);
            *(uint2*)(Al_w + woff) = pk;
        }
#pragma unroll
        for (int r = 0; r < 8; r++) {
            int v = r * 256 + t;
            int n = v >> 4;
            int kk = (v & 15) * 4;
            uint32_t woff = (uint32_t)n * TS_W + (uint32_t)(kk >> 1);
            *(uint2*)(Bh_w + woff) = *(const uint2*)(q2h_base + (size_t)n * 512 + kb + kk);
            *(uint2*)(Bl_w + woff) = *(const uint2*)(q2l_base + (size_t)n * 512 + kb + kk);
        }
        __syncthreads();

#pragma unroll
        for (int ks = 0; ks < 4; ks++) {
            int kw = ks * 8;
            uint32_t bhf[4][2], blf[4][2];
#pragma unroll
            for (int ni = 0; ni < 4; ni++) {
                const uint32_t* ph = Bh_w + (uint32_t)(nb + ni * 8 + gid) * TS_W + kw + tig;
                bhf[ni][0] = ph[0]; bhf[ni][1] = ph[4];
                const uint32_t* pl = Bl_w + (uint32_t)(nb + ni * 8 + gid) * TS_W + kw + tig;
                blf[ni][0] = pl[0]; blf[ni][1] = pl[4];
            }
#pragma unroll
            for (int mi = 0; mi < 4; mi++) {
                const uint32_t* pa = Ah_w + (uint32_t)(mb + mi * 16 + gid) * TS_W + kw + tig;
                uint32_t ah[4];
                ah[0] = pa[0]; ah[1] = pa[8 * TS_W];
                ah[2] = pa[4]; ah[3] = pa[8 * TS_W + 4];
                const uint32_t* pl = Al_w + (uint32_t)(mb + mi * 16 + gid) * TS_W + kw + tig;
                uint32_t al[4];
                al[0] = pl[0]; al[1] = pl[8 * TS_W];
                al[2] = pl[4]; al[3] = pl[8 * TS_W + 4];
#pragma unroll
                for (int ni = 0; ni < 4; ni++) {
                    mma16816(acc[mi][ni], ah, bhf[ni]);
                    mma16816(acc[mi][ni], ah, blf[ni]);
                    mma16816(acc[mi][ni], al, bhf[ni]);
                }
            }
        }
        __syncthreads();
    }

    // ---- epilogue: cos divide + row max ----
    float nc_v[4][2];
#pragma unroll
    for (int ni = 0; ni < 4; ni++) {
        int cb = nb + ni * 8 + 2 * tig;
        nc_v[ni][0] = nc_s[cb];
        nc_v[ni][1] = nc_s[cb + 1];
    }
#pragma unroll
    for (int mi = 0; mi < 4; mi++) {
        int r0 = mb + mi * 16 + gid;
        float na0 = na_s[r0], na1 = na_s[r0 + 8];
        float m0 = -INFINITY, m1 = -INFINITY;
#pragma unroll
        for (int ni = 0; ni < 4; ni++) {
            m0 = fmaxf(m0, acc[mi][ni][0] / fmaxf(na0 * nc_v[ni][0], EPS));
            m0 = fmaxf(m0, acc[mi][ni][1] / fmaxf(na0 * nc_v[ni][1], EPS));
            m1 = fmaxf(m1, acc[mi][ni][2] / fmaxf(na1 * nc_v[ni][0], EPS));
            m1 = fmaxf(m1, acc[mi][ni][3] / fmaxf(na1 * nc_v[ni][1], EPS));
        }
        m0 = fmaxf(m0, __shfl_xor_sync(0xffffffffu, m0, 1));
        m0 = fmaxf(m0, __shfl_xor_sync(0xffffffffu, m0, 2));
        m1 = fmaxf(m1, __shfl_xor_sync(0xffffffffu, m1, 1));
        m1 = fmaxf(m1, __shfl_xor_sync(0xffffffffu, m1, 2));
        if (tig == 0) {
            red[r0 * 4 + wc] = m0;
            red[(r0 + 8) * 4 + wc] = m1;
        }
    }
    __syncthreads();
    if (t < 128) {
        float m = red[t * 4 + 0];
        m = fmaxf(m, red[t * 4 + 1]);
        m = fmaxf(m, red[t * 4 + 2]);
        m = fmaxf(m, red[t * 4 + 3]);
        out[((size_t)b * 128 + t) * 128 + 32 + dir * 16 + p] = m;
    }
}

// ---------------------------------------------------------------------------
// Kernel 4: the six cos_full outputs
// ---------------------------------------------------------------------------
__global__ void k_cosfull(const float* __restrict__ q1, const float* __restrict__ q2,
                          const float* __restrict__ W, float* __restrict__ out) {
    int i = blockIdx.x, b = blockIdx.y;
    int lane = threadIdx.x & 31, warp = threadIdx.x >> 5;

    for (int s = 0; s < 12; s++) {
        int tk = warp + 8 * s;
        int p = tk & 15;
        int rest = tk >> 4;
        int dir = rest & 1, which = rest >> 1;
        int widx = (which == 0) ? dir : ((which == 1) ? 4 + dir : 6 + dir);
        const float* wv = W + (size_t)(widx * 16 + p) * 256;
        const float* x  = q1 + (size_t)b * 65536 + (size_t)i * 512 + dir * 256;
        const float* y;
        float sy = 1.f;
        if (which == 0) {
            int j = (dir == 0) ? 127 : 0;
            y = q2 + (size_t)b * 65536 + (size_t)j * 512 + dir * 256;
        } else if (which == 1) {
            y = &g_meanS[dir][b][i][0];
            float rs = g_rowsum_fw[b][i];
            float bsafe = (rs > EPS) ? rs : EPS;
            sy = 1.f / bsafe;
        } else {
            y = &g_maxat[dir][b][i][0];
        }

        float sxy = 0.f, sxx = 0.f, syy = 0.f;
        for (int h = lane; h < 256; h += 32) {
            float w = wv[h]; float ww = w * w;
            float xv = x[h];
            float yv = y[h] * sy;
            sxy += xv * yv * ww;
            sxx += xv * xv * ww;
            syy += yv * yv * ww;
        }
#pragma unroll
        for (int off = 16; off > 0; off >>= 1) {
            sxy += __shfl_xor_sync(0xffffffffu, sxy, off);
            sxx += __shfl_xor_sync(0xffffffffu, sxx, off);
            syy += __shfl_xor_sync(0xffffffffu, syy, off);
        }
        if (lane == 0) {
            float den = fmaxf(sqrtf(sxx) * sqrtf(syy), EPS);
            int col = ((which == 0) ? 0 : (which == 1) ? 64 : 96) + dir * 16 + p;
            out[((size_t)b * 128 + i) * 128 + col] = sxy / den;
        }
    }
}

// ---------------------------------------------------------------------------
extern "C" void kernel_launch(void* const* d_in, const int* in_sizes, int n_in,
                              void* d_out, int out_size) {
    const float* q1 = (const float*)d_in[0];
    const float* q2 = (const float*)d_in[1];
    const float* W  = (const float*)d_in[2];
    float* out = (float*)d_out;

    cudaFuncSetAttribute(k_attention_mma, cudaFuncAttributeMaxDynamicSharedMemorySize,
                         SMEM_ATT_TOTAL);
    cudaFuncSetAttribute(k_maxpool_mma, cudaFuncAttributeMaxDynamicSharedMemorySize,
                         SMEM_MMA_TOTAL);

    k_split<<<2048, 256>>>(q1, q2);
    k_attention_mma<<<dim3(16, 2), 256, SMEM_ATT_TOTAL>>>(q1, q2);
    k_meanmax<<<dim3(16, 2, 16), 256>>>(q2);
    k_maxpool_mma<<<dim3(16, 16, 2), 256, SMEM_MMA_TOTAL>>>(q1, q2, W, out);
    k_cosfull<<<dim3(128, 16), 256>>>(q1, q2, W, out);
}

// round 13
// speedup vs baseline: 1.7964x; 1.7598x over previous
#include <cuda_runtime.h>
#include <cuda_bf16.h>
#include <cstdint>
#include <math.h>

#define EPS 1e-8f

// Scratch (device globals: no allocation allowed)
__device__ float g_att[2][16][128][128];       // attention matrices (fw/bw)
__device__ float g_rowsum_fw[16][128];         // sum_j att_fw[b,i,j]
__device__ float g_meanS[2][16][128][256];     // att @ q2 (unnormalized mean)
__device__ float g_maxat[2][16][128][256];     // max_j att[i,j]*q2[j,h]
__device__ __nv_bfloat16 g_q1h[16 * 128 * 512];  // q1 hi bf16
__device__ __nv_bfloat16 g_q1l[16 * 128 * 512];  // q1 lo bf16
__device__ __nv_bfloat16 g_q2h[16 * 128 * 512];  // q2 hi bf16
__device__ __nv_bfloat16 g_q2l[16 * 128 * 512];  // q2 lo bf16

// ---------------------------------------------------------------------------
// mma.sync m16n8k16 bf16 (HMMA path — legal on plain sm_103 PTX target)
// ---------------------------------------------------------------------------
__device__ __forceinline__ void mma16816(float* d, const uint32_t* a, const uint32_t* b) {
    asm volatile(
        "mma.sync.aligned.m16n8k16.row.col.f32.bf16.bf16.f32 "
        "{%0,%1,%2,%3}, {%4,%5,%6,%7}, {%8,%9}, {%0,%1,%2,%3};"
        : "+f"(d[0]), "+f"(d[1]), "+f"(d[2]), "+f"(d[3])
        : "r"(a[0]), "r"(a[1]), "r"(a[2]), "r"(a[3]), "r"(b[0]), "r"(b[1]));
}

// ---------------------------------------------------------------------------
// Kernel 0: split q1 AND q2 into hi/lo bf16 (done once)
// ---------------------------------------------------------------------------
__global__ void k_split(const float* __restrict__ q1, const float* __restrict__ q2) {
    int gidx = blockIdx.x * 256 + threadIdx.x;   // 0 .. 524287
    int which = gidx >> 18;                      // 0 = q1, 1 = q2
    int idx = gidx & 0x3FFFF;                    // 0 .. 262143 float4 groups
    const float* src = which ? q2 : q1;
    float4 v = *(const float4*)(src + (size_t)idx * 4);
    __nv_bfloat16 h0 = __float2bfloat16(v.x), h1 = __float2bfloat16(v.y);
    __nv_bfloat16 h2 = __float2bfloat16(v.z), h3 = __float2bfloat16(v.w);
    __nv_bfloat16 l0 = __float2bfloat16(v.x - __bfloat162float(h0));
    __nv_bfloat16 l1 = __float2bfloat16(v.y - __bfloat162float(h1));
    __nv_bfloat16 l2 = __float2bfloat16(v.z - __bfloat162float(h2));
    __nv_bfloat16 l3 = __float2bfloat16(v.w - __bfloat162float(h3));
    uint2 pk;
    pk.x = ((uint32_t)__bfloat16_as_ushort(h1) << 16) | __bfloat16_as_ushort(h0);
    pk.y = ((uint32_t)__bfloat16_as_ushort(h3) << 16) | __bfloat16_as_ushort(h2);
    ((uint2*)(which ? g_q2h : g_q1h))[idx] = pk;
    pk.x = ((uint32_t)__bfloat16_as_ushort(l1) << 16) | __bfloat16_as_ushort(l0);
    pk.y = ((uint32_t)__bfloat16_as_ushort(l3) << 16) | __bfloat16_as_ushort(l2);
    ((uint2*)(which ? g_q2l : g_q1l))[idx] = pk;
}

// ---------------------------------------------------------------------------
// Shared tile geometry
// ---------------------------------------------------------------------------
#define TS_W    36                       // padded tile stride in 32-bit words
#define TILE_B  (128 * TS_W * 4)         // 18432 bytes (128-row tile)
#define TILE32_B (32 * TS_W * 4)         // 4608 bytes (32-row tile)

// ---------------------------------------------------------------------------
// Kernel 1 (HMMA): attention + fused rowsum. M split 4 ways.
// grid (16 b, 2 dir, 4 ms). CTA tile 32x128. 8 warps, each 32x16.
// ---------------------------------------------------------------------------
#define AOFF_N1   0
#define AOFF_N2   256
#define AOFF_RED  1024
#define AOFF_AH   3072
#define AOFF_AL   (AOFF_AH + TILE32_B)
#define AOFF_BH   (AOFF_AH + 2 * TILE32_B)
#define AOFF_BL   (AOFF_AH + 2 * TILE32_B + TILE_B)
#define SMEM_ATT_TOTAL (AOFF_AH + 2 * TILE32_B + 2 * TILE_B)   // 49152

__global__ void __launch_bounds__(256)
k_attention_mma(const float* __restrict__ q1, const float* __restrict__ q2) {
    extern __shared__ char smem[];
    int b = blockIdx.x, dir = blockIdx.y, ms = blockIdx.z;
    int m0 = ms * 32;
    int t = threadIdx.x;
    int wid = t >> 5, lane = t & 31;
    int gid = lane >> 2, tig = lane & 3;
    int nbw = wid * 16;                   // warp col base (8 warps x 16 cols)

    const float* Ag = q1 + ((size_t)b * 128 + m0) * 512 + dir * 256;
    const float* Bg = q2 + (size_t)b * 65536 + dir * 256;

    float* n1_s = (float*)(smem + AOFF_N1);      // [32]
    float* n2_s = (float*)(smem + AOFF_N2);      // [128]
    float* red  = (float*)(smem + AOFF_RED);     // [32][8]
    uint32_t* Ah_w = (uint32_t*)(smem + AOFF_AH);
    uint32_t* Al_w = (uint32_t*)(smem + AOFF_AL);
    uint32_t* Bh_w = (uint32_t*)(smem + AOFF_BH);
    uint32_t* Bl_w = (uint32_t*)(smem + AOFF_BL);

    // exact fp32 norms: t<128 -> q2 rows (n2), t in [128,160) -> q1 rows (n1)
    if (t < 160) {
        int r = (t < 128) ? t : (t - 128);
        const float* src = (t < 128) ? (Bg + (size_t)r * 512) : (Ag + (size_t)r * 512);
        float s = 0.f;
        for (int h = 0; h < 256; h += 4) {
            float4 v = *(const float4*)(src + h);
            s += v.x * v.x + v.y * v.y + v.z * v.z + v.w * v.w;
        }
        if (t < 128) n2_s[r] = sqrtf(s); else n1_s[r] = sqrtf(s);
    }

    float acc[2][2][4] = {};

    const __nv_bfloat16* q1h_base = g_q1h + ((size_t)b * 128 + m0) * 512 + dir * 256;
    const __nv_bfloat16* q1l_base = g_q1l + ((size_t)b * 128 + m0) * 512 + dir * 256;
    const __nv_bfloat16* q2h_base = g_q2h + ((size_t)b * 128) * 512 + dir * 256;
    const __nv_bfloat16* q2l_base = g_q2l + ((size_t)b * 128) * 512 + dir * 256;

    for (int c = 0; c < 4; c++) {
        int kb = c * 64;
        // A chunk: 32 rows x 64 cols = 512 uint2
#pragma unroll
        for (int r = 0; r < 2; r++) {
            int v = r * 256 + t;
            int n = v >> 4;
            int kk = (v & 15) * 4;
            uint32_t woff = (uint32_t)n * TS_W + (uint32_t)(kk >> 1);
            *(uint2*)(Ah_w + woff) = *(const uint2*)(q1h_base + (size_t)n * 512 + kb + kk);
            *(uint2*)(Al_w + woff) = *(const uint2*)(q1l_base + (size_t)n * 512 + kb + kk);
        }
        // B chunk: 128 rows x 64 cols = 2048 uint2
#pragma unroll
        for (int r = 0; r < 8; r++) {
            int v = r * 256 + t;
            int n = v >> 4;
            int kk = (v & 15) * 4;
            uint32_t woff = (uint32_t)n * TS_W + (uint32_t)(kk >> 1);
            *(uint2*)(Bh_w + woff) = *(const uint2*)(q2h_base + (size_t)n * 512 + kb + kk);
            *(uint2*)(Bl_w + woff) = *(const uint2*)(q2l_base + (size_t)n * 512 + kb + kk);
        }
        __syncthreads();

#pragma unroll
        for (int ks = 0; ks < 4; ks++) {
            int kw = ks * 8;
            uint32_t bhf[2][2], blf[2][2];
#pragma unroll
            for (int ni = 0; ni < 2; ni++) {
                const uint32_t* ph = Bh_w + (uint32_t)(nbw + ni * 8 + gid) * TS_W + kw + tig;
                bhf[ni][0] = ph[0]; bhf[ni][1] = ph[4];
                const uint32_t* pl = Bl_w + (uint32_t)(nbw + ni * 8 + gid) * TS_W + kw + tig;
                blf[ni][0] = pl[0]; blf[ni][1] = pl[4];
            }
#pragma unroll
            for (int mi = 0; mi < 2; mi++) {
                const uint32_t* pa = Ah_w + (uint32_t)(mi * 16 + gid) * TS_W + kw + tig;
                uint32_t ah[4];
                ah[0] = pa[0]; ah[1] = pa[8 * TS_W];
                ah[2] = pa[4]; ah[3] = pa[8 * TS_W + 4];
                const uint32_t* pl = Al_w + (uint32_t)(mi * 16 + gid) * TS_W + kw + tig;
                uint32_t al[4];
                al[0] = pl[0]; al[1] = pl[8 * TS_W];
                al[2] = pl[4]; al[3] = pl[8 * TS_W + 4];
#pragma unroll
                for (int ni = 0; ni < 2; ni++) {
                    mma16816(acc[mi][ni], ah, bhf[ni]);
                    mma16816(acc[mi][ni], ah, blf[ni]);
                    mma16816(acc[mi][ni], al, bhf[ni]);
                }
            }
        }
        __syncthreads();
    }

    // ---- epilogue: normalize, store att, fused rowsum ----
    float n2v[2][2];
#pragma unroll
    for (int ni = 0; ni < 2; ni++) {
        int cb = nbw + ni * 8 + 2 * tig;
        n2v[ni][0] = n2_s[cb];
        n2v[ni][1] = n2_s[cb + 1];
    }
#pragma unroll
    for (int mi = 0; mi < 2; mi++) {
        int rloc = mi * 16 + gid;
        float na0 = n1_s[rloc], na1 = n1_s[rloc + 8];
        float s0 = 0.f, s1 = 0.f;
#pragma unroll
        for (int ni = 0; ni < 2; ni++) {
            int cb = nbw + ni * 8 + 2 * tig;
            float d00 = na0 * n2v[ni][0]; d00 = (d00 > EPS) ? d00 : EPS;
            float d01 = na0 * n2v[ni][1]; d01 = (d01 > EPS) ? d01 : EPS;
            float d10 = na1 * n2v[ni][0]; d10 = (d10 > EPS) ? d10 : EPS;
            float d11 = na1 * n2v[ni][1]; d11 = (d11 > EPS) ? d11 : EPS;
            float a00 = acc[mi][ni][0] / d00;
            float a01 = acc[mi][ni][1] / d01;
            float a10 = acc[mi][ni][2] / d10;
            float a11 = acc[mi][ni][3] / d11;
            *(float2*)&g_att[dir][b][m0 + rloc][cb]     = make_float2(a00, a01);
            *(float2*)&g_att[dir][b][m0 + rloc + 8][cb] = make_float2(a10, a11);
            s0 += a00 + a01;
            s1 += a10 + a11;
        }
        s0 += __shfl_xor_sync(0xffffffffu, s0, 1);
        s0 += __shfl_xor_sync(0xffffffffu, s0, 2);
        s1 += __shfl_xor_sync(0xffffffffu, s1, 1);
        s1 += __shfl_xor_sync(0xffffffffu, s1, 2);
        if (tig == 0) {
            red[rloc * 8 + wid] = s0;
            red[(rloc + 8) * 8 + wid] = s1;
        }
    }
    __syncthreads();
    if (dir == 0 && t < 32) {
        float s = 0.f;
#pragma unroll
        for (int w = 0; w < 8; w++) s += red[t * 8 + w];
        g_rowsum_fw[b][m0 + t] = s;
    }
}

// ---------------------------------------------------------------------------
// Kernel 2: meanS / maxat — j-outer, register accumulators.
// ---------------------------------------------------------------------------
__global__ void __launch_bounds__(256)
k_meanmax(const float* __restrict__ q2) {
    int b = blockIdx.x, dir = blockIdx.y, iq = blockIdx.z;
    int i0 = iq * 8;
    __shared__ float2 att_s[8][64];

    const float* src = &g_att[dir][b][i0][0];
    {
        int c = threadIdx.x;
        float4 v0 = *(const float4*)(src + c * 4);
        ((float4*)att_s)[c] = v0;
    }
    __syncthreads();

    int h = threadIdx.x;
    const float* B = q2 + (size_t)b * 65536 + dir * 256 + h;

    float acc[8] = {};
    float mx[8] = {-INFINITY, -INFINITY, -INFINITY, -INFINITY,
                   -INFINITY, -INFINITY, -INFINITY, -INFINITY};

#pragma unroll 4
    for (int j2 = 0; j2 < 64; j2++) {
        float q0 = __ldg(B + (size_t)(2 * j2) * 512);
        float q1 = __ldg(B + (size_t)(2 * j2 + 1) * 512);
#pragma unroll
        for (int i = 0; i < 8; i++) {
            float2 a = att_s[i][j2];
            float v0 = a.x * q0;
            float v1 = a.y * q1;
            acc[i] += v0 + v1;
            mx[i] = fmaxf(mx[i], fmaxf(v0, v1));
        }
    }

#pragma unroll
    for (int i = 0; i < 8; i++) {
        g_meanS[dir][b][i0 + i][h] = acc[i];
        g_maxat[dir][b][i0 + i][h] = mx[i];
    }
}

// ---------------------------------------------------------------------------
// Kernel 3 (HMMA): cos_maxpool. One CTA per (b,p,dir), 2 CTAs/SM forced.
// ---------------------------------------------------------------------------
#define OFF_W2   0
#define OFF_NA   1024
#define OFF_NC   1536
#define OFF_RED  2048
#define OFF_AH   4096
#define OFF_AL   (OFF_AH + TILE_B)
#define OFF_BH   (OFF_AH + 2 * TILE_B)
#define OFF_BL   (OFF_AH + 3 * TILE_B)
#define SMEM_MMA_TOTAL (OFF_AH + 4 * TILE_B)   // 77824

__global__ void __launch_bounds__(256, 2)
k_maxpool_mma(const float* __restrict__ q1, const float* __restrict__ q2,
              const float* __restrict__ W, float* __restrict__ out) {
    extern __shared__ char smem[];
    int b = blockIdx.x, p = blockIdx.y, dir = blockIdx.z;
    int t = threadIdx.x;
    int wid = t >> 5, lane = t & 31;
    int gid = lane >> 2, tig = lane & 3;
    int wr = wid >> 2, wc = wid & 3;
    int mb = wr * 64, nb = wc * 32;

    const float* Ag = q1 + (size_t)b * 65536 + dir * 256;
    const float* Bg = q2 + (size_t)b * 65536 + dir * 256;
    const float* Wp = W + (size_t)((2 + dir) * 16 + p) * 256;

    float* w2s  = (float*)(smem + OFF_W2);
    float* na_s = (float*)(smem + OFF_NA);
    float* nc_s = (float*)(smem + OFF_NC);
    float* red  = (float*)(smem + OFF_RED);
    uint32_t* Ah_w = (uint32_t*)(smem + OFF_AH);
    uint32_t* Al_w = (uint32_t*)(smem + OFF_AL);
    uint32_t* Bh_w = (uint32_t*)(smem + OFF_BH);
    uint32_t* Bl_w = (uint32_t*)(smem + OFF_BL);

    { float w = Wp[t]; w2s[t] = w * w; }
    __syncthreads();

    {
        int r = t & 127;
        const float* src = (t < 128) ? Ag : Bg;
        float s = 0.f;
        for (int h = 0; h < 256; h += 4) {
            float4 v = *(const float4*)(src + (size_t)r * 512 + h);
            s += v.x * v.x * w2s[h] + v.y * v.y * w2s[h + 1]
               + v.z * v.z * w2s[h + 2] + v.w * v.w * w2s[h + 3];
        }
        if (t < 128) na_s[r] = sqrtf(s); else nc_s[r] = sqrtf(s);
    }

    float acc[4][4][4];
#pragma unroll
    for (int mi = 0; mi < 4; mi++)
#pragma unroll
        for (int ni = 0; ni < 4; ni++)
#pragma unroll
            for (int c = 0; c < 4; c++) acc[mi][ni][c] = 0.f;

    const __nv_bfloat16* q2h_base = g_q2h + ((size_t)b * 128) * 512 + dir * 256;
    const __nv_bfloat16* q2l_base = g_q2l + ((size_t)b * 128) * 512 + dir * 256;

    for (int c = 0; c < 4; c++) {
        int kb = c * 64;
        // ---- convert A chunk (q1 .* w2), split hi/lo ----
#pragma unroll
        for (int r = 0; r < 8; r++) {
            int v = r * 256 + t;
            int i = v >> 4;
            int h4 = (v & 15) * 4;
            float4 qa = *(const float4*)(Ag + (size_t)i * 512 + kb + h4);
            float a0 = qa.x * w2s[kb + h4 + 0];
            float a1 = qa.y * w2s[kb + h4 + 1];
            float a2 = qa.z * w2s[kb + h4 + 2];
            float a3 = qa.w * w2s[kb + h4 + 3];
            __nv_bfloat16 h0 = __float2bfloat16(a0), h1 = __float2bfloat16(a1);
            __nv_bfloat16 h2 = __float2bfloat16(a2), h3 = __float2bfloat16(a3);
            __nv_bfloat16 l0 = __float2bfloat16(a0 - __bfloat162float(h0));
            __nv_bfloat16 l1 = __float2bfloat16(a1 - __bfloat162float(h1));
            __nv_bfloat16 l2 = __float2bfloat16(a2 - __bfloat162float(h2));
            __nv_bfloat16 l3 = __float2bfloat16(a3 - __bfloat162float(h3));
            uint32_t woff = (uint32_t)i * TS_W + (uint32_t)(h4 >> 1);
            uint2 pk;
            pk.x = ((uint32_t)__bfloat16_as_ushort(h1) << 16) | __bfloat16_as_ushort(h0);
            pk.y = ((uint32_t)__bfloat16_as_ushort(h3) << 16) | __bfloat16_as_ushort(h2);
            *(uint2*)(Ah_w + woff) = pk;
            pk.x = ((uint32_t)__bfloat16_as_ushort(l1) << 16) | __bfloat16_as_ushort(l0);
            pk.y = ((uint32_t)__bfloat16_as_ushort(l3) << 16) | __bfloat16_as_ushort(l2);
            *(uint2*)(Al_w + woff) = pk;
        }
#pragma unroll
        for (int r = 0; r < 8; r++) {
            int v = r * 256 + t;
            int n = v >> 4;
            int kk = (v & 15) * 4;
            uint32_t woff = (uint32_t)n * TS_W + (uint32_t)(kk >> 1);
            *(uint2*)(Bh_w + woff) = *(const uint2*)(q2h_base + (size_t)n * 512 + kb + kk);
            *(uint2*)(Bl_w + woff) = *(const uint2*)(q2l_base + (size_t)n * 512 + kb + kk);
        }
        __syncthreads();

#pragma unroll
        for (int ks = 0; ks < 4; ks++) {
            int kw = ks * 8;
            uint32_t bhf[4][2], blf[4][2];
#pragma unroll
            for (int ni = 0; ni < 4; ni++) {
                const uint32_t* ph = Bh_w + (uint32_t)(nb + ni * 8 + gid) * TS_W + kw + tig;
                bhf[ni][0] = ph[0]; bhf[ni][1] = ph[4];
                const uint32_t* pl = Bl_w + (uint32_t)(nb + ni * 8 + gid) * TS_W + kw + tig;
                blf[ni][0] = pl[0]; blf[ni][1] = pl[4];
            }
#pragma unroll
            for (int mi = 0; mi < 4; mi++) {
                const uint32_t* pa = Ah_w + (uint32_t)(mb + mi * 16 + gid) * TS_W + kw + tig;
                uint32_t ah[4];
                ah[0] = pa[0]; ah[1] = pa[8 * TS_W];
                ah[2] = pa[4]; ah[3] = pa[8 * TS_W + 4];
                const uint32_t* pl = Al_w + (uint32_t)(mb + mi * 16 + gid) * TS_W + kw + tig;
                uint32_t al[4];
                al[0] = pl[0]; al[1] = pl[8 * TS_W];
                al[2] = pl[4]; al[3] = pl[8 * TS_W + 4];
#pragma unroll
                for (int ni = 0; ni < 4; ni++) {
                    mma16816(acc[mi][ni], ah, bhf[ni]);
                    mma16816(acc[mi][ni], ah, blf[ni]);
                    mma16816(acc[mi][ni], al, bhf[ni]);
                }
            }
        }
        __syncthreads();
    }

    // ---- epilogue: cos divide + row max ----
    float nc_v[4][2];
#pragma unroll
    for (int ni = 0; ni < 4; ni++) {
        int cb = nb + ni * 8 + 2 * tig;
        nc_v[ni][0] = nc_s[cb];
        nc_v[ni][1] = nc_s[cb + 1];
    }
#pragma unroll
    for (int mi = 0; mi < 4; mi++) {
        int r0 = mb + mi * 16 + gid;
        float na0 = na_s[r0], na1 = na_s[r0 + 8];
        float m0 = -INFINITY, m1 = -INFINITY;
#pragma unroll
        for (int ni = 0; ni < 4; ni++) {
            m0 = fmaxf(m0, acc[mi][ni][0] / fmaxf(na0 * nc_v[ni][0], EPS));
            m0 = fmaxf(m0, acc[mi][ni][1] / fmaxf(na0 * nc_v[ni][1], EPS));
            m1 = fmaxf(m1, acc[mi][ni][2] / fmaxf(na1 * nc_v[ni][0], EPS));
            m1 = fmaxf(m1, acc[mi][ni][3] / fmaxf(na1 * nc_v[ni][1], EPS));
        }
        m0 = fmaxf(m0, __shfl_xor_sync(0xffffffffu, m0, 1));
        m0 = fmaxf(m0, __shfl_xor_sync(0xffffffffu, m0, 2));
        m1 = fmaxf(m1, __shfl_xor_sync(0xffffffffu, m1, 1));
        m1 = fmaxf(m1, __shfl_xor_sync(0xffffffffu, m1, 2));
        if (tig == 0) {
            red[r0 * 4 + wc] = m0;
            red[(r0 + 8) * 4 + wc] = m1;
        }
    }
    __syncthreads();
    if (t < 128) {
        float m = red[t * 4 + 0];
        m = fmaxf(m, red[t * 4 + 1]);
        m = fmaxf(m, red[t * 4 + 2]);
        m = fmaxf(m, red[t * 4 + 3]);
        out[((size_t)b * 128 + t) * 128 + 32 + dir * 16 + p] = m;
    }
}

// ---------------------------------------------------------------------------
// Kernel 4: the six cos_full outputs
// ---------------------------------------------------------------------------
__global__ void k_cosfull(const float* __restrict__ q1, const float* __restrict__ q2,
                          const float* __restrict__ W, float* __restrict__ out) {
    int i = blockIdx.x, b = blockIdx.y;
    int lane = threadIdx.x & 31, warp = threadIdx.x >> 5;

    for (int s = 0; s < 12; s++) {
        int tk = warp + 8 * s;
        int p = tk & 15;
        int rest = tk >> 4;
        int dir = rest & 1, which = rest >> 1;
        int widx = (which == 0) ? dir : ((which == 1) ? 4 + dir : 6 + dir);
        const float* wv = W + (size_t)(widx * 16 + p) * 256;
        const float* x  = q1 + (size_t)b * 65536 + (size_t)i * 512 + dir * 256;
        const float* y;
        float sy = 1.f;
        if (which == 0) {
            int j = (dir == 0) ? 127 : 0;
            y = q2 + (size_t)b * 65536 + (size_t)j * 512 + dir * 256;
        } else if (which == 1) {
            y = &g_meanS[dir][b][i][0];
            float rs = g_rowsum_fw[b][i];
            float bsafe = (rs > EPS) ? rs : EPS;
            sy = 1.f / bsafe;
        } else {
            y = &g_maxat[dir][b][i][0];
        }

        float sxy = 0.f, sxx = 0.f, syy = 0.f;
        for (int h = lane; h < 256; h += 32) {
            float w = wv[h]; float ww = w * w;
            float xv = x[h];
            float yv = y[h] * sy;
            sxy += xv * yv * ww;
            sxx += xv * xv * ww;
            syy += yv * yv * ww;
        }
#pragma unroll
        for (int off = 16; off > 0; off >>= 1) {
            sxy += __shfl_xor_sync(0xffffffffu, sxy, off);
            sxx += __shfl_xor_sync(0xffffffffu, sxx, off);
            syy += __shfl_xor_sync(0xffffffffu, syy, off);
        }
        if (lane == 0) {
            float den = fmaxf(sqrtf(sxx) * sqrtf(syy), EPS);
            int col = ((which == 0) ? 0 : (which == 1) ? 64 : 96) + dir * 16 + p;
            out[((size_t)b * 128 + i) * 128 + col] = sxy / den;
        }
    }
}

// ---------------------------------------------------------------------------
extern "C" void kernel_launch(void* const* d_in, const int* in_sizes, int n_in,
                              void* d_out, int out_size) {
    const float* q1 = (const float*)d_in[0];
    const float* q2 = (const float*)d_in[1];
    const float* W  = (const float*)d_in[2];
    float* out = (float*)d_out;

    cudaFuncSetAttribute(k_attention_mma, cudaFuncAttributeMaxDynamicSharedMemorySize,
                         SMEM_ATT_TOTAL);
    cudaFuncSetAttribute(k_maxpool_mma, cudaFuncAttributeMaxDynamicSharedMemorySize,
                         SMEM_MMA_TOTAL);

    k_split<<<2048, 256>>>(q1, q2);
    k_attention_mma<<<dim3(16, 2, 4), 256, SMEM_ATT_TOTAL>>>(q1, q2);
    k_meanmax<<<dim3(16, 2, 16), 256>>>(q2);
    k_maxpool_mma<<<dim3(16, 16, 2), 256, SMEM_MMA_TOTAL>>>(q1, q2, W, out);
    k_cosfull<<<dim3(128, 16), 256>>>(q1, q2, W, out);
}